// round 11
// baseline (speedup 1.0000x reference)
#include <cuda_runtime.h>

#define HH 56
#define WW 56
#define CHW (HH * WW)     // 3136
#define CHW4 (CHW / 4)    // 784
#define NCH 16            // c-chunks (4 channels each)

// grid = 112: bid = h*2 + ph; block covers p = {2*ph, 2*ph+1}. block = 448 threads.
__global__ __launch_bounds__(448)
void fused_shuffle_conv(const float* __restrict__ x,   // [128,56,56]
                        const float* __restrict__ w0,  // [32,2,3,3]
                        const float* __restrict__ w1,  // [4,64]
                        float* __restrict__ out)       // [128,56,56]
{
    __shared__ float4 t4part[NCH][2][2][14]; // [chunk][pl][g][w4]  14336 B
    __shared__ float  t4s[2][2][60];         // [pl][g][w+2]; P[k]=t4[k-2], zeros at 0,1,58,59
    __shared__ float  W5s[32][2][5];         // collapsed 5-tap kernel
    __shared__ float  corr[2][32][2];        // [side][l][g] boundary-correction weights

    const int bid = blockIdx.x;
    const int h   = bid >> 1;
    const int ph  = bid & 1;            // p = 2*ph + pl
    const int tid = threadIdx.x;

    // ---- Phase B: 4 independent LDG.128 (one latency round), 32 FFMA, both p.
    //      tid -> chunk(16) x g(2) x w4(14); lanes walk w4 -> coalesced. (R5 layout)
    {
        const int chunk = tid / 28;
        const int r     = tid % 28;
        const int g     = r / 14;
        const int w4    = r % 14;

        const float4* x4 = (const float4*)x;
        const int rowoff = h * 14 + w4;

        float4 v[4];
        #pragma unroll
        for (int c = 0; c < 4; c++) {
            int cc = chunk * 4 + c;
            v[c] = x4[(size_t)(2 * cc + g) * CHW4 + rowoff];
        }

        float4 acc0 = make_float4(0.f, 0.f, 0.f, 0.f);
        float4 acc1 = make_float4(0.f, 0.f, 0.f, 0.f);
        #pragma unroll
        for (int c = 0; c < 4; c++) {
            float wv0 = __ldg(w1 + (2 * ph + 0) * 64 + chunk * 4 + c);
            float wv1 = __ldg(w1 + (2 * ph + 1) * 64 + chunk * 4 + c);
            acc0.x += v[c].x * wv0;  acc0.y += v[c].y * wv0;
            acc0.z += v[c].z * wv0;  acc0.w += v[c].w * wv0;
            acc1.x += v[c].x * wv1;  acc1.y += v[c].y * wv1;
            acc1.z += v[c].z * wv1;  acc1.w += v[c].w * wv1;
        }
        t4part[chunk][0][g][w4] = acc0;
        t4part[chunk][1][g][w4] = acc1;
    }

    // ---- W5[l][g][d] = sum_{u1+u2=d} w0[l,g,u1,u2]  (320 entries) ----
    if (tid < 320) {
        int l = tid / 10;
        int r = tid % 10;
        int g = r / 5, d = r % 5;
        const float* w0lg = w0 + (l * 2 + g) * 9;
        float s = 0.f;
        #pragma unroll
        for (int u1 = 0; u1 < 3; u1++) {
            int u2 = d - u1;
            if (u2 >= 0 && u2 < 3) s += w0lg[u1 * 3 + u2];
        }
        W5s[l][g][d] = s;
    }

    // ---- boundary corrections: side 0 (w==0): w0[l,g,2,0]; side 1 (w==55): w0[l,g,0,2] ----
    if (tid >= 320 && tid < 448) {
        int e = tid - 320;          // 0..127
        int l = e >> 2, g = (e >> 1) & 1, side = e & 1;
        corr[side][l][g] = __ldg(w0 + (l * 2 + g) * 9 + (side ? 2 : 6));
    }

    // ---- zero t4s padding: positions 0,1,58,59 per (pl,g) ----
    if (tid >= 304 && tid < 320) {
        int e = tid - 304;          // 0..15
        int pl = e >> 3, g = (e >> 2) & 1, k = e & 3;
        t4s[pl][g][(k < 2) ? k : (WW + k)] = 0.f;
    }

    __syncthreads();

    // ---- combine 16 chunk-partials: 224 threads, conflict-free ----
    if (tid < 2 * 2 * WW) {
        const int pl = tid / 112;
        const int g  = (tid / WW) % 2;
        const int w  = tid % WW;
        const float* tp = ((const float*)t4part) + pl * 112 + g * 56 + w;
        float s = 0.f;
        #pragma unroll
        for (int ch = 0; ch < NCH; ch++)
            s += tp[ch * 224];
        t4s[pl][g][w + 2] = s;
    }

    __syncthreads();

    // ---- Phase C (vectorized): thread owns 4 consecutive w, one p, two l values ----
    // tid -> w4 = tid%14, pl = (tid/14)&1, lq = tid/28 in [0,16); l = lq + 16*li, li<2.
    {
        const int w4 = tid % 14;
        const int pl = (tid / 14) & 1;
        const int lq = tid / 28;
        const int p  = 2 * ph + pl;
        const int hout = (h + 1) % HH;

        // taps: t[g][k] = P[pl][g][4*w4 + k], k in [0,8) -> two aligned LDS.128 per g
        float t[2][8];
        #pragma unroll
        for (int g = 0; g < 2; g++) {
            *(float4*)&t[g][0] = *(const float4*)&t4s[pl][g][4 * w4];
            *(float4*)&t[g][4] = *(const float4*)&t4s[pl][g][4 * w4 + 4];
        }

        float4* outp = (float4*)(out + (size_t)hout * WW + 4 * w4 + (size_t)p * CHW);

        #pragma unroll
        for (int li = 0; li < 2; li++) {
            const int l = lq + li * 16;

            float W5r[2][5];
            #pragma unroll
            for (int g = 0; g < 2; g++)
                #pragma unroll
                for (int d = 0; d < 5; d++)
                    W5r[g][d] = W5s[l][g][d];   // warp-broadcast LDS

            float o[4];
            #pragma unroll
            for (int j = 0; j < 4; j++) {
                float acc = 0.f;
                #pragma unroll
                for (int g = 0; g < 2; g++)
                    #pragma unroll
                    for (int d = 0; d < 5; d++)
                        acc += W5r[g][d] * t[g][j + d];
                o[j] = acc;
            }
            // boundary corrections: w==0 -> (w4==0, j==0) uses P[2]=t[g][2];
            //                       w==55 -> (w4==13, j==3) uses P[57]=t[g][5]
            if (w4 == 0)
                o[0] -= corr[0][l][0] * t[0][2] + corr[0][l][1] * t[1][2];
            if (w4 == 13)
                o[3] -= corr[1][l][0] * t[0][5] + corr[1][l][1] * t[1][5];

            outp[(size_t)(l * 4) * (CHW / 4)] = make_float4(o[0], o[1], o[2], o[3]);
        }
    }
}

extern "C" void kernel_launch(void* const* d_in, const int* in_sizes, int n_in,
                              void* d_out, int out_size)
{
    const float* x  = (const float*)d_in[0];   // [1,128,56,56]
    const float* w0 = (const float*)d_in[1];   // [32,2,3,3]
    const float* w1 = (const float*)d_in[2];   // [4,64]
    float* out = (float*)d_out;                // [1,128,56,56]

    fused_shuffle_conv<<<HH * 2, 448>>>(x, w0, w1, out);
}

// round 12
// speedup vs baseline: 1.1015x; 1.1015x over previous
#include <cuda_runtime.h>

#define HH 56
#define WW 56
#define CHW (HH * WW)     // 3136
#define CHW4 (CHW / 4)    // 784
#define NCH 16            // c-chunks (4 channels each)

// grid = 112: bid = h*2 + ph; block covers p = {2*ph, 2*ph+1}. block = 448 threads.
__global__ __launch_bounds__(448)
void fused_shuffle_conv(const float* __restrict__ x,   // [128,56,56]
                        const float* __restrict__ w0,  // [32,2,3,3]
                        const float* __restrict__ w1,  // [4,64]
                        float* __restrict__ out)       // [128,56,56]
{
    __shared__ float4 t4part[NCH][2][2][14]; // [chunk][pl][g][w4]  14336 B
    __shared__ float  t4s[2][2][60];         // [pl][g][w+2]; P[k]=t4[k-2], zeros at 0,1,58,59
    __shared__ float  W5s[32][2][5];         // collapsed 5-tap kernel
    __shared__ float  corr[2][32][2];        // [side][l][g] boundary-correction weights

    const int bid = blockIdx.x;
    const int h   = bid >> 1;
    const int ph  = bid & 1;            // p = 2*ph + pl
    const int tid = threadIdx.x;

    // ---- Phase B: 4 independent LDG.128 (one latency round), 32 FFMA, both p.
    //      tid -> chunk(16) x g(2) x w4(14); lanes walk w4 -> coalesced. (R5 layout)
    {
        const int chunk = tid / 28;
        const int r     = tid % 28;
        const int g     = r / 14;
        const int w4    = r % 14;

        const float4* x4 = (const float4*)x;
        const int rowoff = h * 14 + w4;

        float4 v[4];
        #pragma unroll
        for (int c = 0; c < 4; c++) {
            int cc = chunk * 4 + c;
            v[c] = x4[(size_t)(2 * cc + g) * CHW4 + rowoff];
        }

        float4 acc0 = make_float4(0.f, 0.f, 0.f, 0.f);
        float4 acc1 = make_float4(0.f, 0.f, 0.f, 0.f);
        #pragma unroll
        for (int c = 0; c < 4; c++) {
            float wv0 = __ldg(w1 + (2 * ph + 0) * 64 + chunk * 4 + c);
            float wv1 = __ldg(w1 + (2 * ph + 1) * 64 + chunk * 4 + c);
            acc0.x += v[c].x * wv0;  acc0.y += v[c].y * wv0;
            acc0.z += v[c].z * wv0;  acc0.w += v[c].w * wv0;
            acc1.x += v[c].x * wv1;  acc1.y += v[c].y * wv1;
            acc1.z += v[c].z * wv1;  acc1.w += v[c].w * wv1;
        }
        t4part[chunk][0][g][w4] = acc0;
        t4part[chunk][1][g][w4] = acc1;
    }

    // ---- W5[l][g][d] = sum_{u1+u2=d} w0[l,g,u1,u2]  (320 entries) ----
    if (tid < 320) {
        int l = tid / 10;
        int r = tid % 10;
        int g = r / 5, d = r % 5;
        const float* w0lg = w0 + (l * 2 + g) * 9;
        float s = 0.f;
        #pragma unroll
        for (int u1 = 0; u1 < 3; u1++) {
            int u2 = d - u1;
            if (u2 >= 0 && u2 < 3) s += w0lg[u1 * 3 + u2];
        }
        W5s[l][g][d] = s;
    }

    // ---- boundary corrections: side 0 (w==0): w0[l,g,2,0]; side 1 (w==55): w0[l,g,0,2] ----
    if (tid >= 320 && tid < 448) {
        int e = tid - 320;          // 0..127
        int l = e >> 2, g = (e >> 1) & 1, side = e & 1;
        corr[side][l][g] = __ldg(w0 + (l * 2 + g) * 9 + (side ? 2 : 6));
    }

    // ---- zero t4s padding: positions 0,1,58,59 per (pl,g) ----
    if (tid >= 304 && tid < 320) {
        int e = tid - 304;          // 0..15
        int pl = e >> 3, g = (e >> 2) & 1, k = e & 3;
        t4s[pl][g][(k < 2) ? k : (WW + k)] = 0.f;
    }

    __syncthreads();

    // ---- combine 16 chunk-partials: 224 threads, conflict-free ----
    if (tid < 2 * 2 * WW) {
        const int pl = tid / 112;
        const int g  = (tid / WW) % 2;
        const int w  = tid % WW;
        const float* tp = ((const float*)t4part) + pl * 112 + g * 56 + w;
        float s = 0.f;
        #pragma unroll
        for (int ch = 0; ch < NCH; ch++)
            s += tp[ch * 224];
        t4s[pl][g][w + 2] = s;
    }

    __syncthreads();

    // ---- Phase C (vectorized): thread owns 4 consecutive w, one p, two l values ----
    // tid -> w4 = tid%14, pl = (tid/14)&1, lq = tid/28 in [0,16); l = lq + 16*li, li<2.
    {
        const int w4 = tid % 14;
        const int pl = (tid / 14) & 1;
        const int lq = tid / 28;
        const int p  = 2 * ph + pl;
        const int hout = (h + 1) % HH;

        // taps: t[g][k] = P[pl][g][4*w4 + k], k in [0,8) -> two aligned LDS.128 per g
        float t[2][8];
        #pragma unroll
        for (int g = 0; g < 2; g++) {
            *(float4*)&t[g][0] = *(const float4*)&t4s[pl][g][4 * w4];
            *(float4*)&t[g][4] = *(const float4*)&t4s[pl][g][4 * w4 + 4];
        }

        float4* outp = (float4*)(out + (size_t)hout * WW + 4 * w4 + (size_t)p * CHW);

        #pragma unroll
        for (int li = 0; li < 2; li++) {
            const int l = lq + li * 16;

            float W5r[2][5];
            #pragma unroll
            for (int g = 0; g < 2; g++)
                #pragma unroll
                for (int d = 0; d < 5; d++)
                    W5r[g][d] = W5s[l][g][d];   // warp-broadcast LDS

            float o[4];
            #pragma unroll
            for (int j = 0; j < 4; j++) {
                float acc = 0.f;
                #pragma unroll
                for (int g = 0; g < 2; g++)
                    #pragma unroll
                    for (int d = 0; d < 5; d++)
                        acc += W5r[g][d] * t[g][j + d];
                o[j] = acc;
            }
            // boundary corrections: w==0 -> (w4==0, j==0) uses P[2]=t[g][2];
            //                       w==55 -> (w4==13, j==3) uses P[57]=t[g][5]
            if (w4 == 0)
                o[0] -= corr[0][l][0] * t[0][2] + corr[0][l][1] * t[1][2];
            if (w4 == 13)
                o[3] -= corr[1][l][0] * t[0][5] + corr[1][l][1] * t[1][5];

            outp[(size_t)(l * 4) * (CHW / 4)] = make_float4(o[0], o[1], o[2], o[3]);
        }
    }
}

extern "C" void kernel_launch(void* const* d_in, const int* in_sizes, int n_in,
                              void* d_out, int out_size)
{
    const float* x  = (const float*)d_in[0];   // [1,128,56,56]
    const float* w0 = (const float*)d_in[1];   // [32,2,3,3]
    const float* w1 = (const float*)d_in[2];   // [4,64]
    float* out = (float*)d_out;                // [1,128,56,56]

    fused_shuffle_conv<<<HH * 2, 448>>>(x, w0, w1, out);
}